// round 4
// baseline (speedup 1.0000x reference)
#include <cuda_runtime.h>

// InteractionLayer: per-batch Gram matrix upper triangle.
//   x   : [4096, 64, 128] fp32
//   out : [4096, 2016]    fp32   (strictly upper triangle, row-major i<j)
//
// Round 4: exploit symmetry (compute only upper-triangle tiles) + staged
// coalesced epilogue.
//   - 1 CTA per batch, 160 threads (5 warps).
//   - 4x4 grid of 16x16 big tiles; 10 upper big tiles -> 40 8x8 subtiles.
//     160 threads = 40 subtiles x 4 k-quarters (k=32 each).
//   - fma.rn.f32x2 packed accumulation (validated R3: 60.5% fma-pipe).
//   - Per-lane k rotation keeps every 64-bit LDS conflict-free.
//   - Epilogue: quarters 1-3 dump partials to padded smem (float4,
//     conflict-free), quarter 0 reduces + scatters into a triangle staging
//     buffer, all threads stream it out with coalesced STG.128.

typedef unsigned long long u64;

#define F       64
#define D       128
#define NPAIR   2016
#define NSUB    40     // 10 big upper tiles x 4 subtiles
#define RSTRIDE 68     // padded float stride per subtile in reduction buffer
#define NTHREADS 160

__device__ __forceinline__ u64 ffma2(u64 a, u64 b, u64 c) {
#if defined(__CUDA_ARCH__) && (__CUDA_ARCH__ >= 1000)
    u64 d;
    asm("fma.rn.f32x2 %0, %1, %2, %3;" : "=l"(d) : "l"(a), "l"(b), "l"(c));
    return d;
#else
    float2 af = *(const float2*)&a, bf = *(const float2*)&b, cf = *(const float2*)&c;
    float2 df;
    df.x = fmaf(af.x, bf.x, cf.x);
    df.y = fmaf(af.y, bf.y, cf.y);
    u64 d; *(float2*)&d = df;
    return d;
#endif
}

__global__ void __launch_bounds__(NTHREADS, 2)
gram_upper_kernel(const float* __restrict__ x, float* __restrict__ out) {
    __shared__ float sx[F * D];        // 32 KB; reused as reduction buffer
    __shared__ float s_stage[NPAIR];   // 8 KB triangle staging

    const int tid = threadIdx.x;
    const int b   = blockIdx.x;

    // ---- stage X[b] into smem (coalesced float4)
    {
        const float4* g4 = (const float4*)(x + (size_t)b * (F * D));
        float4* s4 = (float4*)sx;
        #pragma unroll
        for (int i = tid; i < (F * D) / 4; i += NTHREADS)
            s4[i] = g4[i];
    }
    __syncthreads();

    // ---- work assignment: q = k-quarter (0..3), t = subtile (0..39)
    const int q = tid / NSUB;
    const int t = tid - q * NSUB;
    const int T   = t >> 2;      // big 16x16 tile index (upper enum, 0..9)
    const int sub = t & 3;       // 2x2 subtile within big tile
    int bi = 0, rem = T;
    while (rem >= 4 - bi) { rem -= 4 - bi; ++bi; }
    const int bj = bi + rem;
    const int r0 = bi * 16 + ((sub >> 1) << 3);
    const int c0 = bj * 16 + ((sub & 1) << 3);
    const int kbase = q << 5;    // 0,32,64,96

    u64 acc[8][8];
    #pragma unroll
    for (int i = 0; i < 8; ++i)
        #pragma unroll
        for (int j = 0; j < 8; ++j) acc[i][j] = 0ULL;

    // per-lane k rotation: (2*tid) mod 32 distinct within every half-warp
    int kk = (tid * 2) & 31;

    #pragma unroll 4
    for (int it = 0; it < 16; ++it) {
        const float* pk = sx + kbase + kk;
        u64 av[8], bv[8];
        #pragma unroll
        for (int i = 0; i < 8; ++i)
            av[i] = *(const u64*)(pk + (r0 + i) * D);
        #pragma unroll
        for (int j = 0; j < 8; ++j)
            bv[j] = *(const u64*)(pk + (c0 + j) * D);
        #pragma unroll
        for (int i = 0; i < 8; ++i)
            #pragma unroll
            for (int j = 0; j < 8; ++j)
                acc[i][j] = ffma2(av[i], bv[j], acc[i][j]);
        kk = (kk + 2) & 31;
    }

    // ---- horizontal combine of f32x2 lanes
    float p[64];
    #pragma unroll
    for (int i = 0; i < 8; ++i)
        #pragma unroll
        for (int j = 0; j < 8; ++j) {
            u64 v = acc[i][j];
            p[i * 8 + j] = __uint_as_float((unsigned)v) +
                           __uint_as_float((unsigned)(v >> 32));
        }

    // ---- cross-quarter reduction (reuse sx; 3*40*68 = 8160 <= 8192 floats)
    __syncthreads();   // all compute reads of sx done
    float* red = sx;
    if (q != 0) {
        float4* dst = (float4*)(red + (q - 1) * (NSUB * RSTRIDE) + t * RSTRIDE);
        #pragma unroll
        for (int e = 0; e < 16; ++e)
            dst[e] = make_float4(p[4*e], p[4*e+1], p[4*e+2], p[4*e+3]);
    }
    __syncthreads();

    if (q == 0) {
        const float4* r1 = (const float4*)(red + 0 * (NSUB * RSTRIDE) + t * RSTRIDE);
        const float4* r2 = (const float4*)(red + 1 * (NSUB * RSTRIDE) + t * RSTRIDE);
        const float4* r3 = (const float4*)(red + 2 * (NSUB * RSTRIDE) + t * RSTRIDE);
        #pragma unroll
        for (int e = 0; e < 16; ++e) {
            float4 a = r1[e], c = r2[e], d = r3[e];
            p[4*e+0] += a.x + c.x + d.x;
            p[4*e+1] += a.y + c.y + d.y;
            p[4*e+2] += a.z + c.z + d.z;
            p[4*e+3] += a.w + c.w + d.w;
        }
        // scatter into triangle staging
        #pragma unroll
        for (int i = 0; i < 8; ++i) {
            const int row  = r0 + i;
            const int base = row * (125 - row) / 2 - 1;  // + col for col>row
            #pragma unroll
            for (int j = 0; j < 8; ++j) {
                const int col = c0 + j;
                if (col > row)
                    s_stage[base + col] = p[i * 8 + j];
            }
        }
    }
    __syncthreads();

    // ---- coalesced vectorized output
    {
        const float4* st4 = (const float4*)s_stage;
        float4* o4 = (float4*)(out + (size_t)b * NPAIR);
        #pragma unroll
        for (int i = tid; i < NPAIR / 4; i += NTHREADS)
            o4[i] = st4[i];
    }
}

extern "C" void kernel_launch(void* const* d_in, const int* in_sizes, int n_in,
                              void* d_out, int out_size) {
    const float* x = (const float*)d_in[0];
    float* out = (float*)d_out;
    gram_upper_kernel<<<4096, NTHREADS>>>(x, out);
}